// round 9
// baseline (speedup 1.0000x reference)
#include <cuda_runtime.h>
#include <cuda_fp16.h>
#include <cstdint>

// ---------------------------------------------------------------------------
// out[M,N] = segment_mean(gather(cf, member_idx), segment_ids) @ W + b
// R9: single producer/consumer kernel. 148 producer CTAs (wave-1 resident,
// bids 0..147) compute segment means tile-by-tile into g_a (fp16) and set
// per-tile flags; 1564 consumer CTAs spin on their M-tile flag then run the
// R6 fp16 mma.sync GEMM. Gather (L2-bound) overlaps MMA (tensor-bound).
// Prelude: starts[] + flag reset (one kernel), W transpose->fp16.
// ---------------------------------------------------------------------------

#define MAX_ROWS_PAD 65664
#define AK 256
#define NPROD 148

__device__ __half g_a[(size_t)MAX_ROWS_PAD * AK];
__device__ __half g_b[1024 * 512];          // [N][K] (W transposed)
__device__ int g_starts[65600];
__device__ int g_flag[512];

// ---------------------------------------------------------------------------
// PTX helpers (baseline sm_80 features — safe through compute_103 PTX)
// ---------------------------------------------------------------------------
__device__ __forceinline__ uint32_t smem_u32(const void* p) {
    uint32_t a;
    asm("{ .reg .u64 t; cvta.to.shared.u64 t, %1; cvt.u32.u64 %0, t; }"
        : "=r"(a) : "l"(p));
    return a;
}

#define CP16(dst, src) \
    asm volatile("cp.async.cg.shared.global [%0], [%1], 16;" \
                 :: "r"(dst), "l"(src) : "memory")
#define CP_COMMIT() asm volatile("cp.async.commit_group;" ::: "memory")
#define CP_WAIT1()  asm volatile("cp.async.wait_group 1;" ::: "memory")

#define LDM4(r, a) \
    asm volatile("ldmatrix.sync.aligned.m8n8.x4.shared.b16 {%0,%1,%2,%3}, [%4];" \
                 : "=r"((r)[0]), "=r"((r)[1]), "=r"((r)[2]), "=r"((r)[3]) \
                 : "r"(a))

#define MMA_F16(d, a, b0, b1) \
    asm volatile("mma.sync.aligned.m16n8k16.row.col.f32.f16.f16.f32 " \
                 "{%0,%1,%2,%3}, {%4,%5,%6,%7}, {%8,%9}, {%0,%1,%2,%3};" \
                 : "+f"((d)[0]), "+f"((d)[1]), "+f"((d)[2]), "+f"((d)[3]) \
                 : "r"((a)[0]), "r"((a)[1]), "r"((a)[2]), "r"((a)[3]), \
                   "r"(b0), "r"(b1))

#define ACC4(a, v) { (a).x += (v).x; (a).y += (v).y; (a).z += (v).z; (a).w += (v).w; }

// ---------------------------------------------------------------------------
// Kernel 0: segment starts + flag reset
// ---------------------------------------------------------------------------
__global__ void starts_kernel(const int* __restrict__ seg, int num_members, int num_cells) {
    int i = blockIdx.x * blockDim.x + threadIdx.x;
    if (i < 512) g_flag[i] = 0;
    if (i > num_members) return;
    int cur  = (i < num_members) ? __ldg(&seg[i]) : num_cells;
    int prev = (i > 0) ? __ldg(&seg[i - 1]) : -1;
    for (int c = prev + 1; c <= cur; c++) g_starts[c] = i;
}

// ---------------------------------------------------------------------------
// Kernel 1: W prepack -> [N][K] fp16 via smem-tiled transpose
// ---------------------------------------------------------------------------
__global__ void prepw_kernel(const float* __restrict__ W, int K, int N) {
    __shared__ float t[32][33];
    const int kb = blockIdx.x * 32, nb = blockIdx.y * 32;
    const int tx = threadIdx.x, ty = threadIdx.y;
#pragma unroll
    for (int i = 0; i < 4; i++)
        t[ty + i * 8][tx] = W[(size_t)(kb + ty + i * 8) * N + nb + tx];
    __syncthreads();
#pragma unroll
    for (int i = 0; i < 4; i++)
        g_b[(size_t)(nb + ty + i * 8) * K + kb + tx] =
            __float2half_rn(t[tx][ty + i * 8]);
}

// ---------------------------------------------------------------------------
// Fused producer/consumer kernel. 256 threads, 96KB smem, 2 CTAs/SM.
// Producers: bids 0..NPROD-1, grid-stride over M-tiles; 8 groups of 32 lanes,
//   each group serially computes 16 cells of the tile (lane owns 2 float4
//   chunks = 32B of the 1KB row). After the tile: fence + flag.
// Consumers: gbid = bid-NPROD; m = gbid % ntm (ascending first), n = gbid/ntm.
//   Spin on flag[m], then the R6 GEMM (BK=64, 3-stage cp.async, swizzled).
// ---------------------------------------------------------------------------
#define STAGE_BYTES 32768u
#define SEC_BYTES   16384u
#define NSTAGE      3

__global__ __launch_bounds__(256, 2)
void fused_kernel(const float4* __restrict__ cf4,
                  const int* __restrict__ midx,
                  const float* __restrict__ bias,
                  float* __restrict__ C,
                  int M, int N, int K, int ntm) {
    extern __shared__ char smem[];
    const int tid = threadIdx.x;
    const int K4 = K >> 2;

    if (blockIdx.x < NPROD) {
        // ---------------- producer ----------------
        const int lane = tid & 31;
        const int grp  = tid >> 5;            // 0..7
        const int cb   = 2 * lane;            // float4 chunk base (owns cb, cb+1)

        for (int t = blockIdx.x; t < ntm; t += NPROD) {
#pragma unroll 1
            for (int i = 0; i < 16; i++) {
                const int c = t * 128 + grp * 16 + i;
                const int start = __ldg(&g_starts[c]);
                const int end   = __ldg(&g_starts[c + 1]);
                const int cnt   = end - start;

                float4 a0 = make_float4(0.f, 0.f, 0.f, 0.f);
                float4 a1 = a0, b0 = a0, b1 = a0;

                int j = start;
                for (; j + 2 <= end; j += 2) {
                    int i0 = __ldg(&midx[j])     * K4;
                    int i1 = __ldg(&midx[j + 1]) * K4;
                    float4 v00 = cf4[(size_t)i0 + cb], v01 = cf4[(size_t)i0 + cb + 1];
                    float4 v10 = cf4[(size_t)i1 + cb], v11 = cf4[(size_t)i1 + cb + 1];
                    ACC4(a0, v00); ACC4(a1, v01);
                    ACC4(b0, v10); ACC4(b1, v11);
                }
                if (j < end) {
                    int i0 = __ldg(&midx[j]) * K4;
                    float4 v00 = cf4[(size_t)i0 + cb], v01 = cf4[(size_t)i0 + cb + 1];
                    ACC4(a0, v00); ACC4(a1, v01);
                }

                const float inv = 1.0f / fmaxf((float)cnt, 1.0f);
                __half2 h0 = __floats2half2_rn((a0.x + b0.x) * inv, (a0.y + b0.y) * inv);
                __half2 h1 = __floats2half2_rn((a0.z + b0.z) * inv, (a0.w + b0.w) * inv);
                __half2 h2 = __floats2half2_rn((a1.x + b1.x) * inv, (a1.y + b1.y) * inv);
                __half2 h3 = __floats2half2_rn((a1.z + b1.z) * inv, (a1.w + b1.w) * inv);
                uint4 pk;
                pk.x = *(uint32_t*)&h0; pk.y = *(uint32_t*)&h1;
                pk.z = *(uint32_t*)&h2; pk.w = *(uint32_t*)&h3;
                ((uint4*)(g_a + (size_t)c * AK))[lane] = pk;
            }
            __syncthreads();                 // all groups finished this tile
            if (tid == 0) {
                __threadfence();
                atomicExch(&g_flag[t], 1);
            }
        }
        return;
    }

    // ---------------- consumer (R6 GEMM) ----------------
    const int gbid = blockIdx.x - NPROD;
    const int m_t  = gbid % ntm;
    const int n_t  = gbid / ntm;
    const int bm   = m_t * 128, bn = n_t * 128;

    // wait for this M-tile's means
    if (tid == 0) {
        while (atomicAdd(&g_flag[m_t], 0) == 0) __nanosleep(256);
        __threadfence();
    }
    __syncthreads();

    const uint32_t sb = smem_u32(smem);
    const int wid  = tid >> 5, lane = tid & 31;
    const int wm   = wid & 3;
    const int wn   = wid >> 2;
    const size_t rowb = (size_t)K * 2;

    const char* pA = (const char*)g_a + (size_t)bm * rowb;
    const char* pB = (const char*)g_b + (size_t)bn * rowb;

    uint32_t sdst[4];
    int lrow[4], lch[4];
#pragma unroll
    for (int i = 0; i < 4; i++) {
        int idx = i * 256 + tid;
        lrow[i] = idx >> 3;
        lch[i]  = idx & 7;
        sdst[i] = (uint32_t)(lrow[i] * 128 + ((lch[i] ^ (lrow[i] & 7)) << 4));
    }

    float acc[2][8][4];
#pragma unroll
    for (int g = 0; g < 2; g++)
#pragma unroll
        for (int n = 0; n < 8; n++)
#pragma unroll
            for (int j = 0; j < 4; j++) acc[g][n][j] = 0.f;

    const int a_r = (lane & 15);
    const int a_cadd = (lane >> 4);
    const int b_r = (lane & 7) + ((lane >> 4) << 3);
    const int b_cadd = ((lane >> 3) & 1);

    const int nit = K >> 6;

#pragma unroll
    for (int pre = 0; pre < 2; pre++) {
        const uint32_t sbase = sb + (uint32_t)pre * STAGE_BYTES;
        const size_t kt = (size_t)pre * 128;
#pragma unroll
        for (int i = 0; i < 4; i++) {
            CP16(sbase + sdst[i],             pA + (size_t)lrow[i] * rowb + kt + lch[i] * 16);
            CP16(sbase + SEC_BYTES + sdst[i], pB + (size_t)lrow[i] * rowb + kt + lch[i] * 16);
        }
        CP_COMMIT();
    }

    for (int it = 0; it < nit; it++) {
        const uint32_t stg = sb + (uint32_t)(it % NSTAGE) * STAGE_BYTES;
        CP_WAIT1();
        __syncthreads();

        if (it + 2 < nit) {
            const uint32_t sbase = sb + (uint32_t)((it + 2) % NSTAGE) * STAGE_BYTES;
            const size_t kt = (size_t)(it + 2) * 128;
#pragma unroll
            for (int i = 0; i < 4; i++) {
                CP16(sbase + sdst[i],             pA + (size_t)lrow[i] * rowb + kt + lch[i] * 16);
                CP16(sbase + SEC_BYTES + sdst[i], pB + (size_t)lrow[i] * rowb + kt + lch[i] * 16);
            }
            CP_COMMIT();
        } else {
            CP_COMMIT();
        }

#pragma unroll
        for (int s = 0; s < 4; s++) {
            uint32_t af[2][4];
#pragma unroll
            for (int g = 0; g < 2; g++) {
                int row = wm * 32 + g * 16 + a_r;
                int ch  = s * 2 + a_cadd;
                LDM4(af[g], stg + row * 128 + ((ch ^ (row & 7)) << 4));
            }
            uint32_t bf[4][4];
#pragma unroll
            for (int h = 0; h < 4; h++) {
                int row = wn * 64 + h * 16 + b_r;
                int ch  = s * 2 + b_cadd;
                LDM4(bf[h], stg + SEC_BYTES + row * 128 + ((ch ^ (row & 7)) << 4));
            }
#pragma unroll
            for (int h = 0; h < 4; h++)
#pragma unroll
                for (int g = 0; g < 2; g++) {
                    MMA_F16(acc[g][h * 2],     af[g], bf[h][0], bf[h][1]);
                    MMA_F16(acc[g][h * 2 + 1], af[g], bf[h][2], bf[h][3]);
                }
        }
        __syncthreads();
    }

#pragma unroll
    for (int g = 0; g < 2; g++) {
        int row0 = bm + wm * 32 + g * 16 + (lane >> 2);
        int row1 = row0 + 8;
#pragma unroll
        for (int n = 0; n < 8; n++) {
            int col = bn + wn * 64 + n * 8 + (lane & 3) * 2;
            float2 bb = *(const float2*)&bias[col];
            if (row0 < M) {
                float2 o = make_float2(acc[g][n][0] + bb.x, acc[g][n][1] + bb.y);
                *(float2*)&C[(size_t)row0 * N + col] = o;
            }
            if (row1 < M) {
                float2 o = make_float2(acc[g][n][2] + bb.x, acc[g][n][3] + bb.y);
                *(float2*)&C[(size_t)row1 * N + col] = o;
            }
        }
    }
}

// ---------------------------------------------------------------------------
// Launch
// ---------------------------------------------------------------------------
extern "C" void kernel_launch(void* const* d_in, const int* in_sizes, int n_in,
                              void* d_out, int out_size) {
    const float* cf   = (const float*)d_in[0];
    const int* midx   = (const int*)d_in[1];
    const int* seg    = (const int*)d_in[2];
    const float* W    = (const float*)d_in[4];
    const float* bias = (const float*)d_in[5];
    float* out = (float*)d_out;

    const int N = in_sizes[5];           // 512
    const int K = in_sizes[4] / N;       // 256
    const int M = out_size / N;          // 50000
    const int num_members = in_sizes[1]; // 400000
    const int ntm = (M + 127) / 128;     // 391 M-tiles

    cudaFuncSetAttribute(fused_kernel,
                         cudaFuncAttributeMaxDynamicSharedMemorySize,
                         (int)(NSTAGE * STAGE_BYTES));

    starts_kernel<<<(num_members + 256) / 256, 256>>>(seg, num_members, M);
    dim3 tb(32, 8), tg(K / 32, N / 32);
    prepw_kernel<<<tg, tb>>>(W, K, N);

    const int grid = NPROD + ntm * (N / 128);
    fused_kernel<<<grid, 256, NSTAGE * STAGE_BYTES>>>(
        (const float4*)cf, midx, bias, out, M, N, K, ntm);
}